// round 1
// baseline (speedup 1.0000x reference)
#include <cuda_runtime.h>

#define HID   50
#define SEQT  512
#define NB    5          // batch elements per block
#define BLOCK 256        // 5*50 = 250 active threads

__device__ __forceinline__ float sigf(float x) {
    // 1 / (1 + e^-x): MUFU.EX2 + MUFU.RCP path
    return __fdividef(1.0f, 1.0f + __expf(-x));
}
__device__ __forceinline__ float tanhfast(float x) {
    // tanh(x) = 2*sigmoid(2x) - 1
    return __fmaf_rn(2.0f, sigf(2.0f * x), -1.0f);
}

__global__ void __launch_bounds__(BLOCK, 1)
lstm_fused_kernel(const float* __restrict__ x,
                  const float* __restrict__ W_ih,
                  const float* __restrict__ W_hh,
                  const float* __restrict__ b_ih,
                  const float* __restrict__ b_hh,
                  const float* __restrict__ W_out,
                  const float* __restrict__ b_out,
                  float* __restrict__ out,
                  int B)
{
    // double-buffered hidden state, rows padded to 52 floats (208B, 16B aligned)
    __shared__ float sh_h[2][NB][52];
    __shared__ float sh_wout[52];

    const int tid = threadIdx.x;
    int bl = tid / HID;              // local batch index 0..5 (5 == filler)
    int j  = tid - bl * HID;         // hidden unit 0..49
    const bool lane_ok = (bl < NB);
    if (!lane_ok) { bl = 0; j = 0; } // clamp for safe addressing
    const int b = blockIdx.x * NB + bl;
    const bool active = lane_ok && (b < B);
    const int bb = active ? b : 0;

    // ---- one-time init ----
    for (int i = tid; i < 2 * NB * 52; i += BLOCK)
        (&sh_h[0][0][0])[i] = 0.0f;
    if (tid < 52)
        sh_wout[tid] = (tid < HID) ? W_out[tid] : 0.0f;

    // weights into registers: 4 gate rows of W_hh for this hidden unit
    float w[4][HID];
    float wih[4], bs[4];
    #pragma unroll
    for (int g = 0; g < 4; g++) {
        const int row = g * HID + j;       // PyTorch gate order: i, f, g, o
        wih[g] = W_ih[row];
        bs[g]  = b_ih[row] + b_hh[row];
        #pragma unroll
        for (int k = 0; k < HID; k++)
            w[g][k] = W_hh[row * HID + k];
    }
    const float bout = b_out[0];

    const float* __restrict__ xrow = x   + (size_t)bb * SEQT;
    float*       __restrict__ orow = out + (size_t)bb * SEQT;

    float c  = 0.0f;
    float xt = xrow[0];
    int cur = 0;

    __syncthreads();   // h buffer zeroed, wout staged

    for (int t = 0; t < SEQT; t++) {
        // gate accumulators: xg = x_t * W_ih + (b_ih + b_hh)
        float a0 = __fmaf_rn(xt, wih[0], bs[0]);
        float a1 = __fmaf_rn(xt, wih[1], bs[1]);
        float a2 = __fmaf_rn(xt, wih[2], bs[2]);
        float a3 = __fmaf_rn(xt, wih[3], bs[3]);

        // prefetch next x (hidden behind the 200-FMA dot)
        float xnext = (t + 1 < SEQT) ? xrow[t + 1] : 0.0f;

        const float* hptr = &sh_h[cur][bl][0];
        #pragma unroll
        for (int kq = 0; kq < 12; kq++) {
            const float4 hv = *reinterpret_cast<const float4*>(hptr + kq * 4);
            a0 = __fmaf_rn(hv.x, w[0][kq*4+0], a0);
            a1 = __fmaf_rn(hv.x, w[1][kq*4+0], a1);
            a2 = __fmaf_rn(hv.x, w[2][kq*4+0], a2);
            a3 = __fmaf_rn(hv.x, w[3][kq*4+0], a3);
            a0 = __fmaf_rn(hv.y, w[0][kq*4+1], a0);
            a1 = __fmaf_rn(hv.y, w[1][kq*4+1], a1);
            a2 = __fmaf_rn(hv.y, w[2][kq*4+1], a2);
            a3 = __fmaf_rn(hv.y, w[3][kq*4+1], a3);
            a0 = __fmaf_rn(hv.z, w[0][kq*4+2], a0);
            a1 = __fmaf_rn(hv.z, w[1][kq*4+2], a1);
            a2 = __fmaf_rn(hv.z, w[2][kq*4+2], a2);
            a3 = __fmaf_rn(hv.z, w[3][kq*4+2], a3);
            a0 = __fmaf_rn(hv.w, w[0][kq*4+3], a0);
            a1 = __fmaf_rn(hv.w, w[1][kq*4+3], a1);
            a2 = __fmaf_rn(hv.w, w[2][kq*4+3], a2);
            a3 = __fmaf_rn(hv.w, w[3][kq*4+3], a3);
        }
        {
            const float2 hv = *reinterpret_cast<const float2*>(hptr + 48);
            a0 = __fmaf_rn(hv.x, w[0][48], a0);
            a1 = __fmaf_rn(hv.x, w[1][48], a1);
            a2 = __fmaf_rn(hv.x, w[2][48], a2);
            a3 = __fmaf_rn(hv.x, w[3][48], a3);
            a0 = __fmaf_rn(hv.y, w[0][49], a0);
            a1 = __fmaf_rn(hv.y, w[1][49], a1);
            a2 = __fmaf_rn(hv.y, w[2][49], a2);
            a3 = __fmaf_rn(hv.y, w[3][49], a3);
        }

        // LSTM cell update (gate order i, f, g, o)
        const float ig = sigf(a0);
        const float fg = sigf(a1);
        const float gg = tanhfast(a2);
        const float og = sigf(a3);
        c = __fmaf_rn(fg, c, ig * gg);
        const float hn = og * tanhfast(c);

        const int nxt = cur ^ 1;
        if (active) sh_h[nxt][bl][j] = hn;
        __syncthreads();

        // output projection y_t = h_t . W_out + b_out (one thread per batch elem)
        if (active && j == 0) {
            const float* hp = &sh_h[nxt][bl][0];
            float y0 = bout, y1 = 0.0f, y2 = 0.0f, y3 = 0.0f;
            #pragma unroll
            for (int kq = 0; kq < 13; kq++) {   // pads (50,51) are zero in both
                const float4 hv = *reinterpret_cast<const float4*>(hp + kq * 4);
                const float4 wv = *reinterpret_cast<const float4*>(sh_wout + kq * 4);
                y0 = __fmaf_rn(hv.x, wv.x, y0);
                y1 = __fmaf_rn(hv.y, wv.y, y1);
                y2 = __fmaf_rn(hv.z, wv.z, y2);
                y3 = __fmaf_rn(hv.w, wv.w, y3);
            }
            orow[t] = (y0 + y1) + (y2 + y3);
        }

        xt = xnext;
        cur = nxt;
    }
}

extern "C" void kernel_launch(void* const* d_in, const int* in_sizes, int n_in,
                              void* d_out, int out_size)
{
    const float* x     = (const float*)d_in[0];
    const float* W_ih  = (const float*)d_in[1];
    const float* W_hh  = (const float*)d_in[2];
    const float* b_ih  = (const float*)d_in[3];
    const float* b_hh  = (const float*)d_in[4];
    const float* W_out = (const float*)d_in[5];
    const float* b_out = (const float*)d_in[6];
    float* out = (float*)d_out;

    const int B = in_sizes[0] / SEQT;          // I == 1, x is [B, T, 1]
    const int grid = (B + NB - 1) / NB;
    lstm_fused_kernel<<<grid, BLOCK>>>(x, W_ih, W_hh, b_ih, b_hh, W_out, b_out, out, B);
}

// round 2
// speedup vs baseline: 1.0771x; 1.0771x over previous
#include <cuda_runtime.h>

#define HID   50
#define SEQT  512
#define NB    5          // batch elements per block
#define BLOCK 256        // 5*50 = 250 active threads

// packed 2xfp32 FMA: d = a*b + c (elementwise on two floats in a 64-bit reg)
__device__ __forceinline__ unsigned long long fma2(unsigned long long a,
                                                   unsigned long long b,
                                                   unsigned long long c) {
    unsigned long long d;
    asm("fma.rn.f32x2 %0, %1, %2, %3;" : "=l"(d) : "l"(a), "l"(b), "l"(c));
    return d;
}
__device__ __forceinline__ float hsum2(unsigned long long v) {
    float lo, hi;
    asm("mov.b64 {%0, %1}, %2;" : "=f"(lo), "=f"(hi) : "l"(v));
    return lo + hi;
}
__device__ __forceinline__ float tanhapx(float x) {
    float y;
    asm("tanh.approx.f32 %0, %1;" : "=f"(y) : "f"(x));
    return y;
}
__device__ __forceinline__ float sigapx(float x) {
    // sigmoid(x) = 0.5*tanh(x/2) + 0.5   (1 MUFU + 2 FFMA)
    return __fmaf_rn(0.5f, tanhapx(0.5f * x), 0.5f);
}

__global__ void __launch_bounds__(BLOCK, 1)
lstm_fused_kernel(const float* __restrict__ x,
                  const float* __restrict__ W_ih,
                  const float* __restrict__ W_hh,
                  const float* __restrict__ b_ih,
                  const float* __restrict__ b_hh,
                  const float* __restrict__ W_out,
                  const float* __restrict__ b_out,
                  float* __restrict__ out,
                  int B)
{
    // double-buffered hidden state, rows padded to 52 floats (208B = 13*16B)
    __shared__ __align__(16) float sh_h[2][NB][52];
    __shared__ __align__(16) float sh_wout[52];

    const int tid = threadIdx.x;
    int bl = tid / HID;              // local batch index 0..5 (5 == filler)
    int j  = tid - bl * HID;         // hidden unit 0..49
    const bool lane_ok = (bl < NB);
    if (!lane_ok) { bl = 0; j = 0; } // clamp for safe addressing
    const int b = blockIdx.x * NB + bl;
    const bool active = lane_ok && (b < B);
    const int bb = active ? b : 0;

    // ---- one-time init ----
    for (int i = tid; i < 2 * NB * 52; i += BLOCK)
        (&sh_h[0][0][0])[i] = 0.0f;
    if (tid < 52)
        sh_wout[tid] = (tid < HID) ? W_out[tid] : 0.0f;

    // W_hh rows for this unit's 4 gates, pre-packed as f32 pairs (64-bit regs).
    // Row byte offset = row*200 -> 8B aligned, so direct 64-bit loads work.
    unsigned long long w2[4][25];
    float wih[4], bs[4];
    #pragma unroll
    for (int g = 0; g < 4; g++) {
        const int row = g * HID + j;       // PyTorch gate order: i, f, g, o
        wih[g] = W_ih[row];
        bs[g]  = b_ih[row] + b_hh[row];
        const unsigned long long* wrow =
            reinterpret_cast<const unsigned long long*>(W_hh + row * HID);
        #pragma unroll
        for (int p = 0; p < 25; p++)
            w2[g][p] = wrow[p];
    }
    const float bout = b_out[0];

    const float* __restrict__ xrow = x   + (size_t)bb * SEQT;
    float*       __restrict__ orow = out + (size_t)bb * SEQT;

    float c  = 0.0f;
    float xt = xrow[0];
    int cur = 0;

    __syncthreads();   // h buffer zeroed, wout staged

    for (int t = 0; t < SEQT; t++) {
        // packed gate accumulators (both float lanes start at 0.0f)
        unsigned long long acc0 = 0ull, acc1 = 0ull, acc2 = 0ull, acc3 = 0ull;

        // prefetch next x (hidden behind the dot product)
        float xnext = (t + 1 < SEQT) ? xrow[t + 1] : 0.0f;

        const float* hptr = &sh_h[cur][bl][0];
        #pragma unroll
        for (int q = 0; q < 12; q++) {    // h[0..47]: 12 x 16B shared loads
            const ulonglong2 hv =
                *reinterpret_cast<const ulonglong2*>(hptr + q * 4);
            acc0 = fma2(hv.x, w2[0][2*q],   acc0);
            acc1 = fma2(hv.x, w2[1][2*q],   acc1);
            acc2 = fma2(hv.x, w2[2][2*q],   acc2);
            acc3 = fma2(hv.x, w2[3][2*q],   acc3);
            acc0 = fma2(hv.y, w2[0][2*q+1], acc0);
            acc1 = fma2(hv.y, w2[1][2*q+1], acc1);
            acc2 = fma2(hv.y, w2[2][2*q+1], acc2);
            acc3 = fma2(hv.y, w2[3][2*q+1], acc3);
        }
        {   // h[48..49]
            const unsigned long long hv =
                *reinterpret_cast<const unsigned long long*>(hptr + 48);
            acc0 = fma2(hv, w2[0][24], acc0);
            acc1 = fma2(hv, w2[1][24], acc1);
            acc2 = fma2(hv, w2[2][24], acc2);
            acc3 = fma2(hv, w2[3][24], acc3);
        }

        // finish: a_g = sum(acc_g) + x_t*W_ih[g] + bias
        const float a0 = hsum2(acc0) + __fmaf_rn(xt, wih[0], bs[0]);
        const float a1 = hsum2(acc1) + __fmaf_rn(xt, wih[1], bs[1]);
        const float a2 = hsum2(acc2) + __fmaf_rn(xt, wih[2], bs[2]);
        const float a3 = hsum2(acc3) + __fmaf_rn(xt, wih[3], bs[3]);

        // LSTM cell update (gate order i, f, g, o)
        const float ig = sigapx(a0);
        const float fg = sigapx(a1);
        const float gg = tanhapx(a2);
        const float og = sigapx(a3);
        c = __fmaf_rn(fg, c, ig * gg);
        const float hn = og * tanhapx(c);

        const int nxt = cur ^ 1;
        if (active) sh_h[nxt][bl][j] = hn;
        __syncthreads();

        // output projection y_t = h_t . W_out + b_out (one thread per batch elem)
        if (active && j == 0) {
            const float* hp = &sh_h[nxt][bl][0];
            float y0 = bout, y1 = 0.0f, y2 = 0.0f, y3 = 0.0f;
            #pragma unroll
            for (int kq = 0; kq < 13; kq++) {   // pads (50,51) are zero in both
                const float4 hv = *reinterpret_cast<const float4*>(hp + kq * 4);
                const float4 wv = *reinterpret_cast<const float4*>(sh_wout + kq * 4);
                y0 = __fmaf_rn(hv.x, wv.x, y0);
                y1 = __fmaf_rn(hv.y, wv.y, y1);
                y2 = __fmaf_rn(hv.z, wv.z, y2);
                y3 = __fmaf_rn(hv.w, wv.w, y3);
            }
            orow[t] = (y0 + y1) + (y2 + y3);
        }

        xt = xnext;
        cur = nxt;
    }
}

extern "C" void kernel_launch(void* const* d_in, const int* in_sizes, int n_in,
                              void* d_out, int out_size)
{
    const float* x     = (const float*)d_in[0];
    const float* W_ih  = (const float*)d_in[1];
    const float* W_hh  = (const float*)d_in[2];
    const float* b_ih  = (const float*)d_in[3];
    const float* b_hh  = (const float*)d_in[4];
    const float* W_out = (const float*)d_in[5];
    const float* b_out = (const float*)d_in[6];
    float* out = (float*)d_out;

    const int B = in_sizes[0] / SEQT;          // I == 1, x is [B, T, 1]
    const int grid = (B + NB - 1) / NB;
    lstm_fused_kernel<<<grid, BLOCK>>>(x, W_ih, W_hh, b_ih, b_hh, W_out, b_out, out, B);
}